// round 17
// baseline (speedup 1.0000x reference)
#include <cuda_runtime.h>
#include <cstdint>
#include <cstddef>

// ---------------------------------------------------------------------------
// DSDM classifier via mma.sync bf16, 512 threads (16 warps = 8 mg x 2 ng):
//   S = x . A^T ; w = exp(-sqrt(|x|^2+|A|^2-2S)/T) ; out = (W.M)/rowsum(W)
// x[2048,128], A[100000,128], M[100000,100], out[2048,100], T=2.
// Globally balanced schedule: 16 bx * 782 chunks = 12512 units over 152 CTAs
// (max 83 chunks/CTA vs 87 on the old 144-CTA grid). CTAs crossing a bx
// boundary restage the x tile and flush per-segment partials (<=11 per-bx
// slices x 2 k-halves = 22 deterministic partial slices).
// ---------------------------------------------------------------------------

#define CONST_B   2048
#define CONST_D   128
#define CONST_N   100000
#define CONST_C   100

#define NCHUNK    782                 // chunks per bx (NPAD/128)
#define NBX       16                  // batch tiles
#define TOTALCH   (NBX * NCHUNK)      // 12512
#define NCTA      152                 // GB300 SM count
#define NSLICE    11                  // max CTAs covering one bx
#define NSLICE2   (NSLICE * 2)        // 22 (x2 for k-halves)
#define NPAD      100096              // 782 * 128
#define THREADS   512
#define PSTRIDE   112
#define CT        104                 // staged class rows (>=101 needed)

#define NA_BLOCKS  (NPAD / 32)        // 3128 A-prep blocks (32 rows each)
#define NMT_BLOCKS (NPAD / 32)        // 3128 Mt-prep blocks (32 n each)
#define MT_STRIDE  105                // staging row stride (gcd(105,32)=1)
#define PREP_SMEM  (32 * MT_STRIDE * 4)   // 13440 B

// -(1 / (T * ln2)), T = 2
#define NEG_K     (-0.72134752044448169f)

// smem byte offsets (main kernel)
#define SM_XN     0                   // float[128]
#define SM_AN     512                 // 2 bufs x 128 floats
#define SM_X      2048                // 2 halves x 16384 (x tile, bf16 SW128)
#define SM_A      34816               // 2 bufs x (2 halves x 16384)
#define SM_MT     100352              // 2 bufs x (2 halves x 16384)
#define SM_TOTAL  165888

#define SWZ(b)    ((b) ^ (((b) >> 3) & 0x70))

// device scratch (allocation-free; zero-initialized at load, unwritten
// partial slices stay zero forever -> deterministic)
__device__ float g_anorm[NPAD];
__device__ __align__(256) unsigned short g_Abf[(size_t)NPAD * CONST_D];
__device__ __align__(256) unsigned short g_Mt[(size_t)128 * NPAD];
__device__ float g_part[(size_t)NSLICE2 * CONST_B * PSTRIDE];

// ---------------- asm helpers ----------------
__device__ __forceinline__ uint32_t smem_u32(const void* p) {
    uint32_t a;
    asm("{ .reg .u64 t; cvta.to.shared.u64 t, %1; cvt.u32.u64 %0, t; }"
        : "=r"(a) : "l"(p));
    return a;
}
__device__ __forceinline__ uint32_t bfpack(float lo, float hi) {
    uint32_t r;
    asm("cvt.rn.bf16x2.f32 %0, %1, %2;" : "=r"(r) : "f"(hi), "f"(lo));
    return r;
}
__device__ __forceinline__ float fsqrt_a(float x) {
    float r; asm("sqrt.approx.f32 %0, %1;" : "=f"(r) : "f"(x)); return r;
}
__device__ __forceinline__ float fex2(float x) {
    float r; asm("ex2.approx.f32 %0, %1;" : "=f"(r) : "f"(x)); return r;
}
__device__ __forceinline__ void ldsm4(uint32_t* r, uint32_t addr) {
    asm volatile("ldmatrix.sync.aligned.m8n8.x4.shared.b16 {%0,%1,%2,%3}, [%4];"
                 : "=r"(r[0]), "=r"(r[1]), "=r"(r[2]), "=r"(r[3]) : "r"(addr));
}
__device__ __forceinline__ void mma16816(float* c, const uint32_t* a,
                                         uint32_t b0, uint32_t b1) {
    asm volatile(
        "mma.sync.aligned.m16n8k16.row.col.f32.bf16.bf16.f32 "
        "{%0,%1,%2,%3}, {%4,%5,%6,%7}, {%8,%9}, {%0,%1,%2,%3};"
        : "+f"(c[0]), "+f"(c[1]), "+f"(c[2]), "+f"(c[3])
        : "r"(a[0]), "r"(a[1]), "r"(a[2]), "r"(a[3]), "r"(b0), "r"(b1));
}
__device__ __forceinline__ void cpasync16(uint32_t dst, const void* src) {
    asm volatile("cp.async.cg.shared.global [%0], [%1], 16;"
                 :: "r"(dst), "l"(src) : "memory");
}
#define CP_COMMIT asm volatile("cp.async.commit_group;" ::: "memory")
#define CP_WAIT1  asm volatile("cp.async.wait_group 1;" ::: "memory")
#define CP_WAIT0  asm volatile("cp.async.wait_group 0;" ::: "memory")

// ---------------------------------------------------------------------------
// prep_AM: fused prep, small smem for high occupancy.
// Blocks [0, NA_BLOCKS): |A_n|^2 fp32 + A -> bf16, 32 rows/block.
// Padding rows [N, NPAD): anorm = 1e30 (w = 0) and zeroed bf16 row.
// Blocks [NA_BLOCKS, +NMT_BLOCKS): 32-n tile of M -> g_Mt[c][n] bf16 via a
// conflict-free (stride-105) smem transpose; row 100 = 1.0, zero padding.
// ---------------------------------------------------------------------------
__global__ void prep_AM(const float* __restrict__ A, const float* __restrict__ M) {
    extern __shared__ float st[];     // Mt branch: [32][105]
    if (blockIdx.x < NA_BLOCKS) {
        const int lane  = threadIdx.x & 31;
        const int row0  = blockIdx.x * 32 + (threadIdx.x >> 5) * 4;
        #pragma unroll
        for (int r = 0; r < 4; r++) {
            int row = row0 + r;
            if (row >= CONST_N) {
                if (lane == 0) g_anorm[row] = 1e30f;
                reinterpret_cast<uint2*>(g_Abf + (size_t)row * CONST_D)[lane] =
                    make_uint2(0u, 0u);
                continue;
            }
            float4 v = reinterpret_cast<const float4*>(A + (size_t)row * CONST_D)[lane];
            float s = v.x * v.x + v.y * v.y + v.z * v.z + v.w * v.w;
            #pragma unroll
            for (int o = 16; o; o >>= 1) s += __shfl_xor_sync(0xffffffffu, s, o);
            if (lane == 0) g_anorm[row] = s;
            uint2 p = make_uint2(bfpack(v.x, v.y), bfpack(v.z, v.w));
            reinterpret_cast<uint2*>(g_Abf + (size_t)row * CONST_D)[lane] = p;
        }
        return;
    }
    // ---- Mt transpose branch: 32 n-rows, conflict-free staging ----
    const int tid = threadIdx.x;
    const int t0  = (blockIdx.x - NA_BLOCKS) * 32;
    for (int idx = tid; idx < 32 * 25; idx += 256) {
        int r = idx / 25, q = idx % 25;
        int n = t0 + r;
        float4 v = make_float4(0.f, 0.f, 0.f, 0.f);
        if (n < CONST_N)
            v = reinterpret_cast<const float4*>(M + (size_t)n * CONST_C)[q];
        st[r * MT_STRIDE + q * 4 + 0] = v.x;
        st[r * MT_STRIDE + q * 4 + 1] = v.y;
        st[r * MT_STRIDE + q * 4 + 2] = v.z;
        st[r * MT_STRIDE + q * 4 + 3] = v.w;
    }
    __syncthreads();
    for (int idx = tid; idx < CT * 2; idx += 256) {
        int c = idx >> 1, half = idx & 1;
        uint32_t h[8];
        #pragma unroll
        for (int j = 0; j < 8; j++) {
            int nl = half * 16 + j * 2;
            float f0, f1;
            if (c < CONST_C) {
                f0 = st[nl * MT_STRIDE + c];
                f1 = st[(nl + 1) * MT_STRIDE + c];
            } else if (c == CONST_C) {
                f0 = (t0 + nl     < CONST_N) ? 1.f : 0.f;
                f1 = (t0 + nl + 1 < CONST_N) ? 1.f : 0.f;
            } else { f0 = 0.f; f1 = 0.f; }
            h[j] = bfpack(f0, f1);
        }
        uint4* dst = reinterpret_cast<uint4*>(g_Mt + (size_t)c * NPAD + t0 + half * 16);
        dst[0] = make_uint4(h[0], h[1], h[2], h[3]);
        dst[1] = make_uint4(h[4], h[5], h[6], h[7]);
    }
}

// ---------------------------------------------------------------------------
// cp.async staging of one global chunk gc (n0 = (gc % NCHUNK)*128; clamp-free
// thanks to NPAD-sized padded g_Abf / g_Mt / g_anorm).
// ---------------------------------------------------------------------------
__device__ __forceinline__ void stage_chunk(uint32_t sb, int gc, int buf, int tid) {
    const int n0 = (gc % NCHUNK) * 128;
    const int q  = tid & 3;            // 64-byte quarter of a 256-B row
    const int hf = q >> 1;             // 128-B half
    const uint32_t qoff = (uint32_t)(q & 1) * 64;
    {   // A chunk: row nl (0..127), SW128 within each 128-B half-row
        int nl = tid >> 2;
        const char* src = (const char*)(g_Abf + (size_t)(n0 + nl) * CONST_D + hf * 64)
                          + qoff;
        uint32_t dst = sb + SM_A + buf * 32768 + hf * 16384 + (uint32_t)nl * 128;
        uint32_t sw = (uint32_t)(nl & 7) << 4;
        #pragma unroll
        for (int j = 0; j < 4; j++)
            cpasync16(dst + ((qoff + (uint32_t)(j * 16)) ^ sw), src + j * 16);
    }
    {   // Mt chunk: class row c (< CT)
        int c = tid >> 2;
        if (c < CT) {
            const char* src = (const char*)(g_Mt + (size_t)c * NPAD + n0 + hf * 64)
                              + qoff;
            uint32_t dst = sb + SM_MT + buf * 32768 + hf * 16384 + (uint32_t)c * 128;
            uint32_t sw = (uint32_t)(c & 7) << 4;
            #pragma unroll
            for (int j = 0; j < 4; j++)
                cpasync16(dst + ((qoff + (uint32_t)(j * 16)) ^ sw), src + j * 16);
        }
    }
    if (tid < 32)   // anorms (padded with 1e30 -> w=0)
        cpasync16(sb + SM_AN + buf * 512 + tid * 16,
                  (const char*)(g_anorm + n0) + tid * 16);
}

// ---------------------------------------------------------------------------
// flush per-segment accumulator to partial slice (cta - f(bx)) for bx.
// f(bx) = first CTA covering chunk bx*NCHUNK = (19*bx)/2 (exact for 152 CTAs).
// ---------------------------------------------------------------------------
__device__ __forceinline__ void flush_acc(float (&acc)[13][4], int bx, int cta,
                                          int ng, int m0, int lane) {
    const int slice = cta - ((19 * bx) >> 1);
    const int sp2 = slice * 2 + ng;
    const int t4x2 = (lane & 3) * 2;
    int rA = bx * 128 + m0 + (lane >> 2);
    size_t baseA = ((size_t)sp2 * CONST_B + rA) * PSTRIDE;
    size_t baseB = baseA + (size_t)8 * PSTRIDE;
    #pragma unroll
    for (int jt = 0; jt < 13; jt++) {
        int c = 8 * jt + t4x2;
        if (c <= CONST_C) {
            g_part[baseA + c] = acc[jt][0];
            g_part[baseB + c] = acc[jt][2];
        }
        if (c + 1 <= CONST_C) {
            g_part[baseA + c + 1] = acc[jt][1];
            g_part[baseB + c + 1] = acc[jt][3];
        }
        #pragma unroll
        for (int qq = 0; qq < 4; qq++) acc[jt][qq] = 0.f;
    }
}

// ---------------------------------------------------------------------------
// main fused kernel: grid 152 CTAs, globally balanced chunk ranges.
// ---------------------------------------------------------------------------
__global__ void __launch_bounds__(THREADS, 1)
dsdm_mma(const float* __restrict__ x)
{
    extern __shared__ char smem[];
    const uint32_t sb = smem_u32(smem);
    const int tid  = threadIdx.x;
    const int warp = tid >> 5, lane = tid & 31;
    const int mg   = warp >> 1;        // m-group: rows [16mg, 16mg+16)
    const int ng   = warp & 1;         // n/k half
    const int m0   = mg * 16;
    const int cta  = blockIdx.x;
    // balanced range: beg(i) = i*TOTALCH/NCTA = i*1564/19 (exact reduction)
    const int cBeg = cta * 1564 / 19;
    const int cEnd = (cta + 1) * 1564 / 19;

    float* xn_s = reinterpret_cast<float*>(smem + SM_XN);

    // prefetch first chunk
    stage_chunk(sb, cBeg, 0, tid);
    CP_COMMIT;

    // lane maps
    const int aRow = (lane & 7) + ((lane >> 3) & 1) * 8;
    const int aKb  = (lane >> 4) * 16;
    const uint32_t aswr = (uint32_t)(aRow & 7) << 4;
    const int bRow = (lane & 7) + ((lane >> 4) & 1) * 8;
    const int bKb  = ((lane >> 3) & 1) * 16;
    const uint32_t bsw = (uint32_t)(bRow & 7) << 4;
    uint32_t bcol[8];
    #pragma unroll
    for (int kk = 0; kk < 8; kk++)
        bcol[kk] = (uint32_t)(((32 * kk) & 127) + bKb) ^ bsw;
    const int t4x2 = (lane & 3) * 2;

    uint32_t xa[8][4];
    float xn0 = 0.f, xn1 = 0.f;
    float acc[13][4];
    #pragma unroll
    for (int j = 0; j < 13; j++)
        #pragma unroll
        for (int qq = 0; qq < 4; qq++) acc[j][qq] = 0.f;

    int last_bx = -1;

    for (int c = cBeg; c < cEnd; c++) {
        if (c + 1 < cEnd) {
            stage_chunk(sb, c + 1, (c + 1 - cBeg) & 1, tid);
            CP_COMMIT;
            CP_WAIT1;
        } else {
            CP_WAIT0;
        }
        __syncthreads();

        const int bx = c / NCHUNK;
        if (bx != last_bx) {
            if (last_bx >= 0)
                flush_acc(acc, last_bx, cta, ng, m0, lane);
            // ---- (re)stage x tile for this bx + row norms ----
            const int b0 = bx * 128;
            for (int r = warp; r < 128; r += 16) {
                float4 v = reinterpret_cast<const float4*>(
                    x + (size_t)(b0 + r) * CONST_D)[lane];
                float sq = v.x * v.x + v.y * v.y + v.z * v.z + v.w * v.w;
                #pragma unroll
                for (int o = 16; o; o >>= 1) sq += __shfl_xor_sync(0xffffffffu, sq, o);
                if (lane == 0) xn_s[r] = sq;
                uint2 p = make_uint2(bfpack(v.x, v.y), bfpack(v.z, v.w));
                uint32_t off = (uint32_t)r * 128 + (lane & 15) * 8;
                *reinterpret_cast<uint2*>(smem + SM_X + (lane >> 4) * 16384 + SWZ(off)) = p;
            }
            __syncthreads();
            // X fragments: 16m x 128k A-operands, register-resident
            {
                uint32_t rb = sb + SM_X + (uint32_t)(m0 + aRow) * 128;
                #pragma unroll
                for (int kk = 0; kk < 8; kk++) {
                    uint32_t col = (uint32_t)(((32 * kk) & 127) + aKb) ^ aswr;
                    ldsm4(xa[kk], rb + (kk >> 2) * 16384 + col);
                }
            }
            xn0 = xn_s[m0 + (lane >> 2)];
            xn1 = xn_s[m0 + 8 + (lane >> 2)];
            last_bx = bx;
        }

        const int buf = (c - cBeg) & 1;
        const uint32_t aTile = sb + SM_A + buf * 32768;
        const uint32_t mTile = sb + SM_MT + buf * 32768 + ng * 16384;
        const float* an_b = reinterpret_cast<const float*>(smem + SM_AN + buf * 512);

        #pragma unroll
        for (int g = 0; g < 4; g++) {
            const int nb = 64 * ng + 16 * g;

            // GEMM1 slice: S[16m x 16n] (k = 128), B double-buffered in regs
            float sacc[2][4];
            #pragma unroll
            for (int j = 0; j < 2; j++)
                #pragma unroll
                for (int qq = 0; qq < 4; qq++) sacc[j][qq] = 0.f;
            {
                uint32_t rowb = aTile + (uint32_t)(nb + bRow) * 128;
                uint32_t b4[2][4];
                ldsm4(b4[0], rowb + bcol[0]);
                #pragma unroll
                for (int kk = 0; kk < 8; kk++) {
                    if (kk < 7)
                        ldsm4(b4[(kk + 1) & 1],
                              rowb + ((kk + 1) >> 2) * 16384 + bcol[kk + 1]);
                    const uint32_t* c4 = b4[kk & 1];
                    mma16816(sacc[0], xa[kk], c4[0], c4[1]);
                    mma16816(sacc[1], xa[kk], c4[2], c4[3]);
                }
            }

            // epilogue: w = exp2(-K*sqrt(xn+an-2S)) -> A-frag wfc (regs only)
            uint32_t wfc[4];
            #pragma unroll
            for (int j = 0; j < 2; j++) {
                float2 anv = *reinterpret_cast<const float2*>(an_b + nb + 8 * j + t4x2);
                float q0 = fmaxf(fmaf(-2.f, sacc[j][0], xn0 + anv.x), 0.f);
                float q1 = fmaxf(fmaf(-2.f, sacc[j][1], xn0 + anv.y), 0.f);
                float q2 = fmaxf(fmaf(-2.f, sacc[j][2], xn1 + anv.x), 0.f);
                float q3 = fmaxf(fmaf(-2.f, sacc[j][3], xn1 + anv.y), 0.f);
                float w0 = fex2(NEG_K * fsqrt_a(q0));
                float w1 = fex2(NEG_K * fsqrt_a(q1));
                float w2 = fex2(NEG_K * fsqrt_a(q2));
                float w3 = fex2(NEG_K * fsqrt_a(q3));
                wfc[2 * j]     = bfpack(w0, w1);
                wfc[2 * j + 1] = bfpack(w2, w3);
            }

            // GEMM2(g): ACC += W_g . Mt[k-slice g]; B double-buffered in regs.
            const uint32_t colg = ((uint32_t)(32 * g + bKb)) ^ bsw;
            {
                uint32_t b4[2][4];
                ldsm4(b4[0], mTile + (uint32_t)bRow * 128 + colg);
                #pragma unroll
                for (int J = 0; J < 7; J++) {
                    if (J < 6)
                        ldsm4(b4[(J + 1) & 1],
                              mTile + (uint32_t)(16 * (J + 1) + bRow) * 128 + colg);
                    const uint32_t* c4 = b4[J & 1];
                    mma16816(acc[2 * J], wfc, c4[0], c4[1]);
                    if (J < 6)
                        mma16816(acc[2 * J + 1], wfc, c4[2], c4[3]);
                }
            }
        }
        __syncthreads();
    }

    flush_acc(acc, last_bx, cta, ng, m0, lane);
}

// ---------------------------------------------------------------------------
// reduce: deterministic sum over 22 partial slices + normalize, float4 lanes.
// ---------------------------------------------------------------------------
__global__ void reduce_kernel(float* __restrict__ out) {
    int i = blockIdx.x * blockDim.x + threadIdx.x;
    if (i >= CONST_B * 25) return;
    int b = i / 25, q = i % 25;
    float4 num = make_float4(0.f, 0.f, 0.f, 0.f);
    float den = 0.f;
    #pragma unroll
    for (int s = 0; s < NSLICE2; s++) {
        const float* p = g_part + ((size_t)s * CONST_B + b) * PSTRIDE;
        float4 v = *reinterpret_cast<const float4*>(p + q * 4);
        num.x += v.x; num.y += v.y; num.z += v.z; num.w += v.w;
        den += p[CONST_C];
    }
    float inv = 1.f / den;
    float4 r = make_float4(num.x * inv, num.y * inv, num.z * inv, num.w * inv);
    *reinterpret_cast<float4*>(out + (size_t)b * CONST_C + q * 4) = r;
}

// ---------------------------------------------------------------------------
extern "C" void kernel_launch(void* const* d_in, const int* in_sizes, int n_in,
                              void* d_out, int out_size)
{
    const float* x = (const float*)d_in[0];   // [2048, 128]
    const float* A = (const float*)d_in[1];   // [100000, 128]
    const float* M = (const float*)d_in[2];   // [100000, 100]
    float* out = (float*)d_out;               // [2048, 100]

    cudaFuncSetAttribute(dsdm_mma, cudaFuncAttributeMaxDynamicSharedMemorySize,
                         SM_TOTAL);

    prep_AM<<<NA_BLOCKS + NMT_BLOCKS, 256, PREP_SMEM>>>(A, M);
    dsdm_mma<<<NCTA, THREADS, SM_TOTAL>>>(x);
    reduce_kernel<<<(CONST_B * 25 + 255) / 256, 256>>>(out);
}